// round 12
// baseline (speedup 1.0000x reference)
#include <cuda_runtime.h>
#include <cuda.h>
#include <cuda_fp16.h>
#include <cstdint>

// ============================================================================
// GraphConvolution: out = adj[16384,16384] @ (x[16384,64] @ W[64,64]) + bias
//
// Round 12 = Round 11 fused kernel + STAGGERED K-START:
//   CTA bid runs its k-loop starting at iteration it0 = 2*bid (cyclic wrap),
//   so the first B tile it needs is the supT slab it computed ITSELF.
//   Global all-CTA barrier replaced by per-slab monotonic flags
//   (g_slab_flag[128], epoch math, replay-safe). Producer polls a flag only
//   on slab transitions (128 polls / 256 iters) + fence.proxy.async.
// Consumer mainloop / epilogue identical to round 11.
// ============================================================================

#define N_ROWS 16384
#define K_DIM  16384
#define IN_F   64
#define OUT_F  64

#define TILE_M 128
#define TILE_K 64
#define STAGES 5
#define N_ITERS (K_DIM / TILE_K)        // 256

#define OFF_A0 0                        // 128 rows x 128B (k 0-31)  = 16384
#define OFF_A1 16384                    // 128 rows x 128B (k 32-63) = 16384
#define OFF_B  32768                    // 64 rows x 128B (fp16 k64) = 8192
#define STAGE_BYTES 40960

#define OFF_BARS   0                    // per stage: full @ 16*s, empty @ 16*s+8
#define OFF_TARGET 128                  // u32: epoch target from t0 to producer
#define OFF_TILES  1024
#define OFF_W      (OFF_TILES + STAGES * STAGE_BYTES)        // 205824
#define SMEM_BYTES (OFF_W + IN_F * OUT_F * 4)                // 222208

#define N_CWARPS 8
#define PART_STRIDE 66                  // padded row stride (floats)

// ---------------------------------------------------------------- PTX helpers
__device__ __forceinline__ uint32_t smem_to_u32(const void* p) {
    uint32_t a;
    asm("{ .reg .u64 t; cvta.to.shared.u64 t, %1; cvt.u32.u64 %0, t; }" : "=r"(a) : "l"(p));
    return a;
}

#define MBARRIER_INIT(addr, count) \
    asm volatile("mbarrier.init.shared.b64 [%0], %1;" :: "r"((uint32_t)(addr)), "r"((uint32_t)(count)) : "memory")

#define MBARRIER_ARRIVE(addr) \
    asm volatile("mbarrier.arrive.shared.b64 _, [%0];" :: "r"((uint32_t)(addr)) : "memory")

#define MBARRIER_EXPECT_TX(addr, bytes) \
    asm volatile("mbarrier.arrive.expect_tx.shared.b64 _, [%0], %1;" :: "r"((uint32_t)(addr)), "r"((uint32_t)(bytes)) : "memory")

#define MBARRIER_WAIT_PARITY(addr, parity) do {                                      \
    uint32_t _mbar = (uint32_t)(addr);                                               \
    uint32_t _par  = (uint32_t)(parity);                                             \
    uint32_t _done;                                                                  \
    asm volatile(                                                                    \
        "{\n\t.reg .pred p;\n\t"                                                     \
        "mbarrier.try_wait.parity.acquire.cta.shared::cta.b64 p, [%1], %2;\n\t"      \
        "selp.b32 %0, 1, 0, p;\n\t}"                                                 \
        : "=r"(_done) : "r"(_mbar), "r"(_par) : "memory");                           \
    if (!_done) {                                                                    \
        asm volatile(                                                                \
            "{\n\t.reg .pred P1;\n\t"                                                \
            "WAIT_LOOP_%=:\n\t"                                                      \
            "mbarrier.try_wait.parity.acquire.cta.shared::cta.b64 P1, [%0], %1, 0x989680;\n\t" \
            "@P1 bra.uni WAIT_DONE_%=;\n\t"                                          \
            "bra.uni WAIT_LOOP_%=;\n\t"                                              \
            "WAIT_DONE_%=:\n\t}"                                                     \
            :: "r"(_mbar), "r"(_par) : "memory");                                    \
    }                                                                                \
} while (0)

__device__ __forceinline__ void tma_load_2d_g(uint32_t smem_addr, const CUtensorMap* map,
                                              int cx, int cy, uint32_t mbar) {
    asm volatile(
        "cp.async.bulk.tensor.2d.shared::cta.global.tile.mbarrier::complete_tx::bytes "
        "[%0], [%1, {%2, %3}], [%4];"
        :: "r"(smem_addr), "l"(map), "r"(cx), "r"(cy), "r"(mbar) : "memory");
}

__device__ __forceinline__ uint32_t lds32(uint32_t a) {
    uint32_t v;
    asm volatile("ld.shared.b32 %0, [%1];" : "=r"(v) : "r"(a));
    return v;
}

__device__ __forceinline__ float2 lds64(uint32_t a) {
    float2 v;
    asm volatile("ld.shared.v2.f32 {%0, %1}, [%2];" : "=f"(v.x), "=f"(v.y) : "r"(a));
    return v;
}

// pack two fp32 -> fp16x2: result.lo = lo, result.hi = hi
__device__ __forceinline__ uint32_t packh2(float hi, float lo) {
    uint32_t d;
    asm("cvt.rn.f16x2.f32 %0, %1, %2;" : "=r"(d) : "f"(hi), "f"(lo));
    return d;
}

__device__ __forceinline__ void mma_f16(float* c,
                                        uint32_t a0, uint32_t a1, uint32_t a2, uint32_t a3,
                                        uint32_t b0, uint32_t b1) {
    asm volatile(
        "mma.sync.aligned.m16n8k16.row.col.f32.f16.f16.f32 "
        "{%0,%1,%2,%3}, {%4,%5,%6,%7}, {%8,%9}, {%0,%1,%2,%3};"
        : "+f"(c[0]), "+f"(c[1]), "+f"(c[2]), "+f"(c[3])
        : "r"(a0), "r"(a1), "r"(a2), "r"(a3), "r"(b0), "r"(b1));
}

// ---------------------------------------------------------------- scratch
__device__ __align__(1024) __half g_supT[(size_t)OUT_F * K_DIM];  // 2 MiB
__device__ unsigned int g_slab_flag[N_ROWS / TILE_M];  // monotonic, per-slab

// ---------------------------------------------------------------- kernel
// 9 warps: wid 0..7 compute (4 row groups x 2 kgroups) + supT prologue,
// wid 8 = TMA producer (pre-issues A, gates each B on its slab flag).
__global__ void __launch_bounds__(288, 1) gcn_gemm_kernel(
    const __grid_constant__ CUtensorMap madj,
    const __grid_constant__ CUtensorMap msup,
    float* __restrict__ out,
    const float* __restrict__ bias,
    const float* __restrict__ x,
    const float* __restrict__ w)
{
    extern __shared__ char smem[];
    uint32_t sb = smem_to_u32(smem);
    int tid = threadIdx.x;
    int wid = tid >> 5;
    int lid = tid & 31;
    int m0 = blockIdx.x * TILE_M;
    int it0 = blockIdx.x * 2;           // staggered start: own slab first

    if (tid == 0) {
        asm volatile("st.shared.u32 [%0], 0;" :: "r"(sb + OFF_TARGET));
        for (int s = 0; s < STAGES; s++) {
            MBARRIER_INIT(sb + OFF_BARS + s * 16, 1);            // full: 1 expect_tx
            MBARRIER_INIT(sb + OFF_BARS + s * 16 + 8, N_CWARPS); // empty: 8 arrives
        }
    }
    __syncthreads();

    if (wid == 8) {
        if (lid == 0) {
            // ---- pre-issue: expect_tx + A loads for ALL stages (B gated)
            for (int s = 0; s < STAGES; s++) {
                uint32_t fb = sb + OFF_BARS + s * 16;
                MBARRIER_EXPECT_TX(fb, STAGE_BYTES);
                uint32_t st = sb + OFF_TILES + s * STAGE_BYTES;
                int idx = (it0 + s) & (N_ITERS - 1);
                tma_load_2d_g(st + OFF_A0, &madj, idx * TILE_K,      m0, fb);
                tma_load_2d_g(st + OFF_A1, &madj, idx * TILE_K + 32, m0, fb);
            }
            // ---- epoch target from this CTA's own publish (t0 writes it)
            unsigned target;
            do {
                asm volatile("ld.acquire.cta.shared.u32 %0, [%1];"
                             : "=r"(target) : "r"(sb + OFF_TARGET));
            } while (target == 0);

            int last_slab = -1;
            // ---- B loads for the pre-issued stages (gated per slab)
            for (int s = 0; s < STAGES; s++) {
                int idx = (it0 + s) & (N_ITERS - 1);
                int slab = idx >> 1;
                if (slab != last_slab) {
                    unsigned v;
                    do {
                        asm volatile("ld.acquire.gpu.global.u32 %0, [%1];"
                                     : "=r"(v) : "l"(g_slab_flag + slab));
                    } while (v < target);
                    asm volatile("fence.proxy.async;" ::: "memory");
                    last_slab = slab;
                }
                uint32_t fb = sb + OFF_BARS + s * 16;
                uint32_t st = sb + OFF_TILES + s * STAGE_BYTES;
                tma_load_2d_g(st + OFF_B, &msup, idx * TILE_K, 0, fb);
            }
            // ---- steady-state pipeline
            int s = 0; uint32_t ph = 0;
            for (int it = STAGES; it < N_ITERS; it++) {
                int idx = (it0 + it) & (N_ITERS - 1);
                int slab = idx >> 1;
                uint32_t fb = sb + OFF_BARS + s * 16;
                MBARRIER_WAIT_PARITY(fb + 8, ph);
                MBARRIER_EXPECT_TX(fb, STAGE_BYTES);
                if (slab != last_slab) {
                    unsigned v;
                    do {
                        asm volatile("ld.acquire.gpu.global.u32 %0, [%1];"
                                     : "=r"(v) : "l"(g_slab_flag + slab));
                    } while (v < target);
                    asm volatile("fence.proxy.async;" ::: "memory");
                    last_slab = slab;
                }
                uint32_t st = sb + OFF_TILES + s * STAGE_BYTES;
                int k0 = idx * TILE_K;
                tma_load_2d_g(st + OFF_B,  &msup, k0,      0,  fb);
                tma_load_2d_g(st + OFF_A0, &madj, k0,      m0, fb);
                tma_load_2d_g(st + OFF_A1, &madj, k0 + 32, m0, fb);
                if (++s == STAGES) { s = 0; ph ^= 1; }
            }
        }
        return;
    }

    // ======== supT prologue (256 compute threads) ========
    {
        // stage W into smem, coalesced
        for (int i = tid; i < IN_F * OUT_F / 4; i += 256)
            reinterpret_cast<float4*>(smem + OFF_W)[i] =
                reinterpret_cast<const float4*>(w)[i];
        asm volatile("bar.sync 2, 256;" ::: "memory");

        int p  = tid & 63;            // k-pair index
        int ng = tid >> 6;            // 0..3 -> 16-wide n group
        int n0 = ng * 16;
        size_t k0 = (size_t)blockIdx.x * 128 + 2u * (unsigned)p;
        const float4* xa4 = reinterpret_cast<const float4*>(x + k0 * IN_F);
        const float4* xb4 = reinterpret_cast<const float4*>(x + (k0 + 1) * IN_F);
        const float4* wv  = reinterpret_cast<const float4*>(smem + OFF_W) + (n0 >> 2);

        float a0[16], a1[16];
#pragma unroll
        for (int j = 0; j < 16; j++) { a0[j] = 0.f; a1[j] = 0.f; }

#pragma unroll
        for (int ii = 0; ii < IN_F / 4; ii++) {
            float4 xa = xa4[ii], xb = xb4[ii];
#pragma unroll
            for (int u = 0; u < 4; u++) {
                int i = ii * 4 + u;
                float va = (u == 0) ? xa.x : (u == 1) ? xa.y : (u == 2) ? xa.z : xa.w;
                float vb = (u == 0) ? xb.x : (u == 1) ? xb.y : (u == 2) ? xb.z : xb.w;
                const float4* wr = wv + i * (OUT_F / 4);
#pragma unroll
                for (int j = 0; j < 4; j++) {
                    float4 q = wr[j];
                    a0[4 * j + 0] = fmaf(va, q.x, a0[4 * j + 0]);
                    a0[4 * j + 1] = fmaf(va, q.y, a0[4 * j + 1]);
                    a0[4 * j + 2] = fmaf(va, q.z, a0[4 * j + 2]);
                    a0[4 * j + 3] = fmaf(va, q.w, a0[4 * j + 3]);
                    a1[4 * j + 0] = fmaf(vb, q.x, a1[4 * j + 0]);
                    a1[4 * j + 1] = fmaf(vb, q.y, a1[4 * j + 1]);
                    a1[4 * j + 2] = fmaf(vb, q.z, a1[4 * j + 2]);
                    a1[4 * j + 3] = fmaf(vb, q.w, a1[4 * j + 3]);
                }
            }
        }
        // write 16 fp16x2 (k0 even -> .lo = k0, .hi = k0+1), coalesced per warp
        uint32_t* dst = reinterpret_cast<uint32_t*>(g_supT);
        size_t kh = k0 >> 1;
#pragma unroll
        for (int j = 0; j < 16; j++)
            dst[(size_t)(n0 + j) * (K_DIM / 2) + kh] = packh2(a1[j], a0[j]);

        __threadfence();
        asm volatile("bar.sync 2, 256;" ::: "memory");
        if (tid == 0) {
            unsigned my;
            asm volatile("atom.add.release.gpu.global.u32 %0, [%1], 1;"
                         : "=r"(my) : "l"(g_slab_flag + blockIdx.x) : "memory");
            unsigned target = my + 1;             // this replay's epoch
            asm volatile("st.release.cta.shared.u32 [%0], %1;"
                         :: "r"(sb + OFF_TARGET), "r"(target) : "memory");
        }
    }

    // ======== mainloop (round-8 structure, stage ring order) ========
    int cwid   = wid & 3;      // row group: rows [32*cwid, 32*cwid+32)
    int kgroup = wid >> 2;     // owns k32 half: 0 -> k0-31, 1 -> k32-63
    int g = lid >> 2;          // 0..7
    int t = lid & 3;           // 0..3
    uint32_t xorv = (uint32_t)g << 4;   // SW128 swizzle term (rows used == g mod 8)

    uint32_t rA0 = (uint32_t)(cwid * 32 + g) * 128;
    uint32_t rB[8];
#pragma unroll
    for (int nt = 0; nt < 8; nt++) rB[nt] = (uint32_t)(nt * 8 + g) * 128;

    uint32_t cA0[2], cA1[2], cB0[2], cB1[2];
#pragma unroll
    for (int ks2 = 0; ks2 < 2; ks2++) {
        cA0[ks2] = ((uint32_t)(ks2 * 64 + 8 * t))      ^ xorv;
        cA1[ks2] = ((uint32_t)(ks2 * 64 + 8 * t + 32)) ^ xorv;
        uint32_t kk = (uint32_t)(kgroup * 2 + ks2);
        cB0[ks2] = (kk * 32 + 4 * t)      ^ xorv;
        cB1[ks2] = (kk * 32 + 4 * t + 16) ^ xorv;
    }

    float acc[2][8][4];
#pragma unroll
    for (int mt = 0; mt < 2; mt++)
#pragma unroll
        for (int nt = 0; nt < 8; nt++)
#pragma unroll
            for (int c = 0; c < 4; c++) acc[mt][nt][c] = 0.f;

    int s = 0; uint32_t ph = 0;
    for (int it = 0; it < N_ITERS; it++) {
        uint32_t fb = sb + OFF_BARS + s * 16;
        MBARRIER_WAIT_PARITY(fb, ph);
        uint32_t st = sb + OFF_TILES + s * STAGE_BYTES;
        uint32_t aB = st + (kgroup ? OFF_A1 : OFF_A0);
        uint32_t bB = st + OFF_B;

#pragma unroll
        for (int ks2 = 0; ks2 < 2; ks2++) {
            uint32_t a0, a1, a2, a3, a4, a5, a6, a7;
            float2 p;
            p = lds64(aB + rA0 +        cA0[ks2]); a0 = packh2(p.y, p.x);
            p = lds64(aB + rA0 + 1024 + cA0[ks2]); a1 = packh2(p.y, p.x);
            p = lds64(aB + rA0 +        cA1[ks2]); a2 = packh2(p.y, p.x);
            p = lds64(aB + rA0 + 1024 + cA1[ks2]); a3 = packh2(p.y, p.x);
            p = lds64(aB + rA0 + 2048 + cA0[ks2]); a4 = packh2(p.y, p.x);
            p = lds64(aB + rA0 + 3072 + cA0[ks2]); a5 = packh2(p.y, p.x);
            p = lds64(aB + rA0 + 2048 + cA1[ks2]); a6 = packh2(p.y, p.x);
            p = lds64(aB + rA0 + 3072 + cA1[ks2]); a7 = packh2(p.y, p.x);

#pragma unroll
            for (int nt = 0; nt < 8; nt++) {
                uint32_t b0 = lds32(bB + rB[nt] + cB0[ks2]);
                uint32_t b1 = lds32(bB + rB[nt] + cB1[ks2]);
                mma_f16(acc[0][nt], a0, a1, a2, a3, b0, b1);
                mma_f16(acc[1][nt], a4, a5, a6, a7, b0, b1);
            }
        }
        if (lid == 0) MBARRIER_ARRIVE(fb + 8);
        if (++s == STAGES) { s = 0; ph ^= 1; }
    }

    // -------- drain barrier: all compute warps done reading tile smem
    asm volatile("bar.sync 1, 256;" ::: "memory");

    // -------- reduction: kgroup 1 writes partials to smem, kgroup 0 adds
    float* part = reinterpret_cast<float*>(smem + OFF_TILES);
    if (kgroup == 1) {
#pragma unroll
        for (int mt = 0; mt < 2; mt++) {
            int r0 = cwid * 32 + mt * 16 + g;
#pragma unroll
            for (int nt = 0; nt < 8; nt++) {
                int col = nt * 8 + 2 * t;
                *reinterpret_cast<float2*>(part + (size_t)r0 * PART_STRIDE + col) =
                    make_float2(acc[mt][nt][0], acc[mt][nt][1]);
                *reinterpret_cast<float2*>(part + (size_t)(r0 + 8) * PART_STRIDE + col) =
                    make_float2(acc[mt][nt][2], acc[mt][nt][3]);
            }
        }
    }
    asm volatile("bar.sync 1, 256;" ::: "memory");

    if (kgroup == 0) {
        const float2* b2 = reinterpret_cast<const float2*>(bias);
        int row0 = m0 + cwid * 32 + g;
#pragma unroll
        for (int mt = 0; mt < 2; mt++) {
            int rloc = cwid * 32 + mt * 16 + g;
            int r = row0 + mt * 16;
#pragma unroll
            for (int nt = 0; nt < 8; nt++) {
                int col = nt * 8 + 2 * t;
                float2 bv = b2[col >> 1];
                float2 p0 = *reinterpret_cast<const float2*>(part + (size_t)rloc * PART_STRIDE + col);
                float2 p1 = *reinterpret_cast<const float2*>(part + (size_t)(rloc + 8) * PART_STRIDE + col);
                *reinterpret_cast<float2*>(out + (size_t)r * OUT_F + col) =
                    make_float2(acc[mt][nt][0] + p0.x + bv.x, acc[mt][nt][1] + p0.y + bv.y);
                *reinterpret_cast<float2*>(out + (size_t)(r + 8) * OUT_F + col) =
                    make_float2(acc[mt][nt][2] + p1.x + bv.x, acc[mt][nt][3] + p1.y + bv.y);
            }
        }
    }
}

// ---------------------------------------------------------------- host
typedef CUresult (*tmap_encode_fn)(
    CUtensorMap*, CUtensorMapDataType, cuuint32_t, void*,
    const cuuint64_t*, const cuuint64_t*, const cuuint32_t*, const cuuint32_t*,
    CUtensorMapInterleave, CUtensorMapSwizzle, CUtensorMapL2promotion,
    CUtensorMapFloatOOBfill);

extern "C" void kernel_launch(void* const* d_in, const int* in_sizes, int n_in,
                              void* d_out, int out_size) {
    const float* x    = (const float*)d_in[0];
    const float* adj  = (const float*)d_in[1];
    const float* w    = (const float*)d_in[2];
    const float* bias = (const float*)d_in[3];
    float* out = (float*)d_out;

    void* supT_ptr = nullptr;
    cudaGetSymbolAddress(&supT_ptr, g_supT);
    __half* supT = (__half*)supT_ptr;

    // Driver entry point via cudart (no -lcuda link dependency)
    tmap_encode_fn enc = nullptr;
    cudaDriverEntryPointQueryResult qr;
    cudaGetDriverEntryPointByVersion("cuTensorMapEncodeTiled", (void**)&enc, 12000,
                                     cudaEnableDefault, &qr);

    CUtensorMap madj{}, msup{};
    {
        cuuint64_t dims[2]    = {(cuuint64_t)K_DIM, (cuuint64_t)N_ROWS};
        cuuint64_t strides[1] = {(cuuint64_t)K_DIM * sizeof(float)};
        cuuint32_t box[2]     = {32, TILE_M};       // 128B x 128 rows, SW128
        cuuint32_t es[2]      = {1, 1};
        enc(&madj, CU_TENSOR_MAP_DATA_TYPE_FLOAT32, 2, (void*)adj,
            dims, strides, box, es,
            CU_TENSOR_MAP_INTERLEAVE_NONE, CU_TENSOR_MAP_SWIZZLE_128B,
            CU_TENSOR_MAP_L2_PROMOTION_L2_128B, CU_TENSOR_MAP_FLOAT_OOB_FILL_NONE);
    }
    {
        cuuint64_t dims[2]    = {(cuuint64_t)K_DIM, (cuuint64_t)OUT_F};
        cuuint64_t strides[1] = {(cuuint64_t)K_DIM * sizeof(__half)};
        cuuint32_t box[2]     = {64, OUT_F};        // 64 fp16 = 128B x 64 rows, SW128
        cuuint32_t es[2]      = {1, 1};
        enc(&msup, CU_TENSOR_MAP_DATA_TYPE_FLOAT16, 2, (void*)supT,
            dims, strides, box, es,
            CU_TENSOR_MAP_INTERLEAVE_NONE, CU_TENSOR_MAP_SWIZZLE_128B,
            CU_TENSOR_MAP_L2_PROMOTION_L2_128B, CU_TENSOR_MAP_FLOAT_OOB_FILL_NONE);
    }

    cudaFuncSetAttribute(gcn_gemm_kernel, cudaFuncAttributeMaxDynamicSharedMemorySize,
                         SMEM_BYTES);
    gcn_gemm_kernel<<<N_ROWS / TILE_M, 288, SMEM_BYTES>>>(madj, msup, out, bias, x, w);
}

// round 13
// speedup vs baseline: 1.0616x; 1.0616x over previous
#include <cuda_runtime.h>
#include <cuda.h>
#include <cuda_fp16.h>
#include <cstdint>

// ============================================================================
// GraphConvolution: out = adj[16384,16384] @ (x[16384,64] @ W[64,64]) + bias
//
// Round 13 = Round 11 (best, 181.7us: fused supT prologue + global epoch
// barrier + round-8 gemm) + L2 PREFETCH of upcoming A tiles during the
// prologue window (DRAM was idle there): producer issues 4 x 128KB
// cp.async.bulk.prefetch.tensor.2d.L2 covering iters 5..20 (64MB chip-wide,
// ~= the idle window's DRAM capacity). Round-12 staggered start reverted
// (per-slab polls on the producer's critical path cost ~11us).
// ============================================================================

#define N_ROWS 16384
#define K_DIM  16384
#define IN_F   64
#define OUT_F  64

#define TILE_M 128
#define TILE_K 64
#define STAGES 5
#define N_ITERS (K_DIM / TILE_K)        // 256

#define OFF_A0 0                        // 128 rows x 128B (k 0-31)  = 16384
#define OFF_A1 16384                    // 128 rows x 128B (k 32-63) = 16384
#define OFF_B  32768                    // 64 rows x 128B (fp16 k64) = 8192
#define STAGE_BYTES 40960

#define OFF_BARS   0                    // per stage: full @ 16*s, empty @ 16*s+8
#define OFF_TARGET 128                  // u32: epoch target from t0 to producer
#define OFF_TILES  1024
#define OFF_W      (OFF_TILES + STAGES * STAGE_BYTES)        // 205824
#define SMEM_BYTES (OFF_W + IN_F * OUT_F * 4)                // 222208

#define N_CWARPS 8
#define PART_STRIDE 66                  // padded row stride (floats)

#define PREF_BOXES 4                    // 4 x 256 cols x 128 rows fp32 = 512KB/CTA

// ---------------------------------------------------------------- PTX helpers
__device__ __forceinline__ uint32_t smem_to_u32(const void* p) {
    uint32_t a;
    asm("{ .reg .u64 t; cvta.to.shared.u64 t, %1; cvt.u32.u64 %0, t; }" : "=r"(a) : "l"(p));
    return a;
}

#define MBARRIER_INIT(addr, count) \
    asm volatile("mbarrier.init.shared.b64 [%0], %1;" :: "r"((uint32_t)(addr)), "r"((uint32_t)(count)) : "memory")

#define MBARRIER_ARRIVE(addr) \
    asm volatile("mbarrier.arrive.shared.b64 _, [%0];" :: "r"((uint32_t)(addr)) : "memory")

#define MBARRIER_EXPECT_TX(addr, bytes) \
    asm volatile("mbarrier.arrive.expect_tx.shared.b64 _, [%0], %1;" :: "r"((uint32_t)(addr)), "r"((uint32_t)(bytes)) : "memory")

#define MBARRIER_WAIT_PARITY(addr, parity) do {                                      \
    uint32_t _mbar = (uint32_t)(addr);                                               \
    uint32_t _par  = (uint32_t)(parity);                                             \
    uint32_t _done;                                                                  \
    asm volatile(                                                                    \
        "{\n\t.reg .pred p;\n\t"                                                     \
        "mbarrier.try_wait.parity.acquire.cta.shared::cta.b64 p, [%1], %2;\n\t"      \
        "selp.b32 %0, 1, 0, p;\n\t}"                                                 \
        : "=r"(_done) : "r"(_mbar), "r"(_par) : "memory");                           \
    if (!_done) {                                                                    \
        asm volatile(                                                                \
            "{\n\t.reg .pred P1;\n\t"                                                \
            "WAIT_LOOP_%=:\n\t"                                                      \
            "mbarrier.try_wait.parity.acquire.cta.shared::cta.b64 P1, [%0], %1, 0x989680;\n\t" \
            "@P1 bra.uni WAIT_DONE_%=;\n\t"                                          \
            "bra.uni WAIT_LOOP_%=;\n\t"                                              \
            "WAIT_DONE_%=:\n\t}"                                                     \
            :: "r"(_mbar), "r"(_par) : "memory");                                    \
    }                                                                                \
} while (0)

__device__ __forceinline__ void tma_load_2d_g(uint32_t smem_addr, const CUtensorMap* map,
                                              int cx, int cy, uint32_t mbar) {
    asm volatile(
        "cp.async.bulk.tensor.2d.shared::cta.global.tile.mbarrier::complete_tx::bytes "
        "[%0], [%1, {%2, %3}], [%4];"
        :: "r"(smem_addr), "l"(map), "r"(cx), "r"(cy), "r"(mbar) : "memory");
}

__device__ __forceinline__ void tma_prefetch_l2(const CUtensorMap* map, int cx, int cy) {
    asm volatile(
        "cp.async.bulk.prefetch.tensor.2d.L2.global.tile [%0, {%1, %2}];"
        :: "l"(map), "r"(cx), "r"(cy) : "memory");
}

__device__ __forceinline__ uint32_t lds32(uint32_t a) {
    uint32_t v;
    asm volatile("ld.shared.b32 %0, [%1];" : "=r"(v) : "r"(a));
    return v;
}

__device__ __forceinline__ float2 lds64(uint32_t a) {
    float2 v;
    asm volatile("ld.shared.v2.f32 {%0, %1}, [%2];" : "=f"(v.x), "=f"(v.y) : "r"(a));
    return v;
}

// pack two fp32 -> fp16x2: result.lo = lo, result.hi = hi
__device__ __forceinline__ uint32_t packh2(float hi, float lo) {
    uint32_t d;
    asm("cvt.rn.f16x2.f32 %0, %1, %2;" : "=r"(d) : "f"(hi), "f"(lo));
    return d;
}

__device__ __forceinline__ void mma_f16(float* c,
                                        uint32_t a0, uint32_t a1, uint32_t a2, uint32_t a3,
                                        uint32_t b0, uint32_t b1) {
    asm volatile(
        "mma.sync.aligned.m16n8k16.row.col.f32.f16.f16.f32 "
        "{%0,%1,%2,%3}, {%4,%5,%6,%7}, {%8,%9}, {%0,%1,%2,%3};"
        : "+f"(c[0]), "+f"(c[1]), "+f"(c[2]), "+f"(c[3])
        : "r"(a0), "r"(a1), "r"(a2), "r"(a3), "r"(b0), "r"(b1));
}

// ---------------------------------------------------------------- scratch
__device__ __align__(1024) __half g_supT[(size_t)OUT_F * K_DIM];  // 2 MiB
__device__ unsigned int g_ready;   // monotonic; target via epoch math

// ---------------------------------------------------------------- kernel
// 9 warps: wid 0..7 compute (4 row groups x 2 kgroups) + supT prologue,
// wid 8 = TMA producer (pre-issues A + L2 prefetch, defers B until ready).
__global__ void __launch_bounds__(288, 1) gcn_gemm_kernel(
    const __grid_constant__ CUtensorMap madj,
    const __grid_constant__ CUtensorMap msup,
    const __grid_constant__ CUtensorMap mpref,
    float* __restrict__ out,
    const float* __restrict__ bias,
    const float* __restrict__ x,
    const float* __restrict__ w)
{
    extern __shared__ char smem[];
    uint32_t sb = smem_to_u32(smem);
    int tid = threadIdx.x;
    int wid = tid >> 5;
    int lid = tid & 31;
    int m0 = blockIdx.x * TILE_M;

    if (tid == 0) {
        asm volatile("st.shared.u32 [%0], 0;" :: "r"(sb + OFF_TARGET));
        for (int s = 0; s < STAGES; s++) {
            MBARRIER_INIT(sb + OFF_BARS + s * 16, 1);            // full: 1 expect_tx
            MBARRIER_INIT(sb + OFF_BARS + s * 16 + 8, N_CWARPS); // empty: 8 arrives
        }
    }
    __syncthreads();

    if (wid == 8) {
        if (lid == 0) {
            // ---- pre-issue: expect_tx + A loads for ALL stages (B deferred)
            for (int s = 0; s < STAGES; s++) {
                uint32_t fb = sb + OFF_BARS + s * 16;
                MBARRIER_EXPECT_TX(fb, STAGE_BYTES);
                uint32_t st = sb + OFF_TILES + s * STAGE_BYTES;
                tma_load_2d_g(st + OFF_A0, &madj, s * TILE_K,      m0, fb);
                tma_load_2d_g(st + OFF_A1, &madj, s * TILE_K + 32, m0, fb);
            }
            // ---- L2 prefetch of A for iters 5..20 (fills prologue DRAM idle)
            for (int pb = 0; pb < PREF_BOXES; pb++)
                tma_prefetch_l2(&mpref, STAGES * TILE_K + pb * 256, m0);
            // ---- wait for this CTA's epoch target (from t0)
            unsigned target;
            do {
                asm volatile("ld.acquire.cta.shared.u32 %0, [%1];"
                             : "=r"(target) : "r"(sb + OFF_TARGET));
            } while (target == 0);
            // ---- wait for all 128 CTAs to publish their supT slabs
            unsigned v;
            do {
                asm volatile("ld.acquire.gpu.global.u32 %0, [%1];"
                             : "=r"(v) : "l"(&g_ready));
            } while (v < target);
            asm volatile("fence.proxy.async;" ::: "memory");
            // ---- deferred B loads for the pre-issued stages
            for (int s = 0; s < STAGES; s++) {
                uint32_t fb = sb + OFF_BARS + s * 16;
                uint32_t st = sb + OFF_TILES + s * STAGE_BYTES;
                tma_load_2d_g(st + OFF_B, &msup, s * TILE_K, 0, fb);
            }
            // ---- steady-state pipeline
            int s = 0; uint32_t ph = 0;
            for (int it = STAGES; it < N_ITERS; it++) {
                uint32_t fb = sb + OFF_BARS + s * 16;
                MBARRIER_WAIT_PARITY(fb + 8, ph);
                MBARRIER_EXPECT_TX(fb, STAGE_BYTES);
                uint32_t st = sb + OFF_TILES + s * STAGE_BYTES;
                int k0 = it * TILE_K;
                tma_load_2d_g(st + OFF_B,  &msup, k0,      0,  fb);
                tma_load_2d_g(st + OFF_A0, &madj, k0,      m0, fb);
                tma_load_2d_g(st + OFF_A1, &madj, k0 + 32, m0, fb);
                if (++s == STAGES) { s = 0; ph ^= 1; }
            }
        }
        return;
    }

    // ======== supT prologue (256 compute threads) ========
    {
        // stage W into smem, coalesced
        for (int i = tid; i < IN_F * OUT_F / 4; i += 256)
            reinterpret_cast<float4*>(smem + OFF_W)[i] =
                reinterpret_cast<const float4*>(w)[i];
        asm volatile("bar.sync 2, 256;" ::: "memory");

        int p  = tid & 63;            // k-pair index
        int ng = tid >> 6;            // 0..3 -> 16-wide n group
        int n0 = ng * 16;
        size_t k0 = (size_t)blockIdx.x * 128 + 2u * (unsigned)p;
        const float4* xa4 = reinterpret_cast<const float4*>(x + k0 * IN_F);
        const float4* xb4 = reinterpret_cast<const float4*>(x + (k0 + 1) * IN_F);
        const float4* wv  = reinterpret_cast<const float4*>(smem + OFF_W) + (n0 >> 2);

        float a0[16], a1[16];
#pragma unroll
        for (int j = 0; j < 16; j++) { a0[j] = 0.f; a1[j] = 0.f; }

#pragma unroll
        for (int ii = 0; ii < IN_F / 4; ii++) {
            float4 xa = xa4[ii], xb = xb4[ii];
#pragma unroll
            for (int u = 0; u < 4; u++) {
                int i = ii * 4 + u;
                float va = (u == 0) ? xa.x : (u == 1) ? xa.y : (u == 2) ? xa.z : xa.w;
                float vb = (u == 0) ? xb.x : (u == 1) ? xb.y : (u == 2) ? xb.z : xb.w;
                const float4* wr = wv + i * (OUT_F / 4);
#pragma unroll
                for (int j = 0; j < 4; j++) {
                    float4 q = wr[j];
                    a0[4 * j + 0] = fmaf(va, q.x, a0[4 * j + 0]);
                    a0[4 * j + 1] = fmaf(va, q.y, a0[4 * j + 1]);
                    a0[4 * j + 2] = fmaf(va, q.z, a0[4 * j + 2]);
                    a0[4 * j + 3] = fmaf(va, q.w, a0[4 * j + 3]);
                    a1[4 * j + 0] = fmaf(vb, q.x, a1[4 * j + 0]);
                    a1[4 * j + 1] = fmaf(vb, q.y, a1[4 * j + 1]);
                    a1[4 * j + 2] = fmaf(vb, q.z, a1[4 * j + 2]);
                    a1[4 * j + 3] = fmaf(vb, q.w, a1[4 * j + 3]);
                }
            }
        }
        // write 16 fp16x2 (k0 even -> .lo = k0, .hi = k0+1), coalesced per warp
        uint32_t* dst = reinterpret_cast<uint32_t*>(g_supT);
        size_t kh = k0 >> 1;
#pragma unroll
        for (int j = 0; j < 16; j++)
            dst[(size_t)(n0 + j) * (K_DIM / 2) + kh] = packh2(a1[j], a0[j]);

        __threadfence();
        asm volatile("bar.sync 2, 256;" ::: "memory");
        if (tid == 0) {
            unsigned my;
            asm volatile("atom.add.release.gpu.global.u32 %0, [%1], 1;"
                         : "=r"(my) : "l"(&g_ready) : "memory");
            unsigned target = ((my >> 7) + 1) << 7;   // 128 * (replay_epoch + 1)
            asm volatile("st.release.cta.shared.u32 [%0], %1;"
                         :: "r"(sb + OFF_TARGET), "r"(target) : "memory");
        }
    }

    // ======== mainloop (round-8 structure, unchanged) ========
    int cwid   = wid & 3;      // row group: rows [32*cwid, 32*cwid+32)
    int kgroup = wid >> 2;     // owns k32 half: 0 -> k0-31, 1 -> k32-63
    int g = lid >> 2;          // 0..7
    int t = lid & 3;           // 0..3
    uint32_t xorv = (uint32_t)g << 4;   // SW128 swizzle term (rows used == g mod 8)

    uint32_t rA0 = (uint32_t)(cwid * 32 + g) * 128;
    uint32_t rB[8];
#pragma unroll
    for (int nt = 0; nt < 8; nt++) rB[nt] = (uint32_t)(nt * 8 + g) * 128;

    uint32_t cA0[2], cA1[2], cB0[2], cB1[2];
#pragma unroll
    for (int ks2 = 0; ks2 < 2; ks2++) {
        cA0[ks2] = ((uint32_t)(ks2 * 64 + 8 * t))      ^ xorv;
        cA1[ks2] = ((uint32_t)(ks2 * 64 + 8 * t + 32)) ^ xorv;
        uint32_t kk = (uint32_t)(kgroup * 2 + ks2);
        cB0[ks2] = (kk * 32 + 4 * t)      ^ xorv;
        cB1[ks2] = (kk * 32 + 4 * t + 16) ^ xorv;
    }

    float acc[2][8][4];
#pragma unroll
    for (int mt = 0; mt < 2; mt++)
#pragma unroll
        for (int nt = 0; nt < 8; nt++)
#pragma unroll
            for (int c = 0; c < 4; c++) acc[mt][nt][c] = 0.f;

    int s = 0; uint32_t ph = 0;
    for (int it = 0; it < N_ITERS; it++) {
        uint32_t fb = sb + OFF_BARS + s * 16;
        MBARRIER_WAIT_PARITY(fb, ph);
        uint32_t st = sb + OFF_TILES + s * STAGE_BYTES;
        uint32_t aB = st + (kgroup ? OFF_A1 : OFF_A0);
        uint32_t bB = st + OFF_B;

#pragma unroll
        for (int ks2 = 0; ks2 < 2; ks2++) {
            uint32_t a0, a1, a2, a3, a4, a5, a6, a7;
            float2 p;
            p = lds64(aB + rA0 +        cA0[ks2]); a0 = packh2(p.y, p.x);
            p = lds64(aB + rA0 + 1024 + cA0[ks2]); a1 = packh2(p.y, p.x);
            p = lds64(aB + rA0 +        cA1[ks2]); a2 = packh2(p.y, p.x);
            p = lds64(aB + rA0 + 1024 + cA1[ks2]); a3 = packh2(p.y, p.x);
            p = lds64(aB + rA0 + 2048 + cA0[ks2]); a4 = packh2(p.y, p.x);
            p = lds64(aB + rA0 + 3072 + cA0[ks2]); a5 = packh2(p.y, p.x);
            p = lds64(aB + rA0 + 2048 + cA1[ks2]); a6 = packh2(p.y, p.x);
            p = lds64(aB + rA0 + 3072 + cA1[ks2]); a7 = packh2(p.y, p.x);

#pragma unroll
            for (int nt = 0; nt < 8; nt++) {
                uint32_t b0 = lds32(bB + rB[nt] + cB0[ks2]);
                uint32_t b1 = lds32(bB + rB[nt] + cB1[ks2]);
                mma_f16(acc[0][nt], a0, a1, a2, a3, b0, b1);
                mma_f16(acc[1][nt], a4, a5, a6, a7, b0, b1);
            }
        }
        if (lid == 0) MBARRIER_ARRIVE(fb + 8);
        if (++s == STAGES) { s = 0; ph ^= 1; }
    }

    // -------- drain barrier: all compute warps done reading tile smem
    asm volatile("bar.sync 1, 256;" ::: "memory");

    // -------- reduction: kgroup 1 writes partials to smem, kgroup 0 adds
    float* part = reinterpret_cast<float*>(smem + OFF_TILES);
    if (kgroup == 1) {
#pragma unroll
        for (int mt = 0; mt < 2; mt++) {
            int r0 = cwid * 32 + mt * 16 + g;
#pragma unroll
            for (int nt = 0; nt < 8; nt++) {
                int col = nt * 8 + 2 * t;
                *reinterpret_cast<float2*>(part + (size_t)r0 * PART_STRIDE + col) =
                    make_float2(acc[mt][nt][0], acc[mt][nt][1]);
                *reinterpret_cast<float2*>(part + (size_t)(r0 + 8) * PART_STRIDE + col) =
                    make_float2(acc[mt][nt][2], acc[mt][nt][3]);
            }
        }
    }
    asm volatile("bar.sync 1, 256;" ::: "memory");

    if (kgroup == 0) {
        const float2* b2 = reinterpret_cast<const float2*>(bias);
        int row0 = m0 + cwid * 32 + g;
#pragma unroll
        for (int mt = 0; mt < 2; mt++) {
            int rloc = cwid * 32 + mt * 16 + g;
            int r = row0 + mt * 16;
#pragma unroll
            for (int nt = 0; nt < 8; nt++) {
                int col = nt * 8 + 2 * t;
                float2 bv = b2[col >> 1];
                float2 p0 = *reinterpret_cast<const float2*>(part + (size_t)rloc * PART_STRIDE + col);
                float2 p1 = *reinterpret_cast<const float2*>(part + (size_t)(rloc + 8) * PART_STRIDE + col);
                *reinterpret_cast<float2*>(out + (size_t)r * OUT_F + col) =
                    make_float2(acc[mt][nt][0] + p0.x + bv.x, acc[mt][nt][1] + p0.y + bv.y);
                *reinterpret_cast<float2*>(out + (size_t)(r + 8) * OUT_F + col) =
                    make_float2(acc[mt][nt][2] + p1.x + bv.x, acc[mt][nt][3] + p1.y + bv.y);
            }
        }
    }
}

// ---------------------------------------------------------------- host
typedef CUresult (*tmap_encode_fn)(
    CUtensorMap*, CUtensorMapDataType, cuuint32_t, void*,
    const cuuint64_t*, const cuuint64_t*, const cuuint32_t*, const cuuint32_t*,
    CUtensorMapInterleave, CUtensorMapSwizzle, CUtensorMapL2promotion,
    CUtensorMapFloatOOBfill);

extern "C" void kernel_launch(void* const* d_in, const int* in_sizes, int n_in,
                              void* d_out, int out_size) {
    const float* x    = (const float*)d_in[0];
    const float* adj  = (const float*)d_in[1];
    const float* w    = (const float*)d_in[2];
    const float* bias = (const float*)d_in[3];
    float* out = (float*)d_out;

    void* supT_ptr = nullptr;
    cudaGetSymbolAddress(&supT_ptr, g_supT);
    __half* supT = (__half*)supT_ptr;

    // Driver entry point via cudart (no -lcuda link dependency)
    tmap_encode_fn enc = nullptr;
    cudaDriverEntryPointQueryResult qr;
    cudaGetDriverEntryPointByVersion("cuTensorMapEncodeTiled", (void**)&enc, 12000,
                                     cudaEnableDefault, &qr);

    CUtensorMap madj{}, msup{}, mpref{};
    {
        cuuint64_t dims[2]    = {(cuuint64_t)K_DIM, (cuuint64_t)N_ROWS};
        cuuint64_t strides[1] = {(cuuint64_t)K_DIM * sizeof(float)};
        cuuint32_t box[2]     = {32, TILE_M};       // 128B x 128 rows, SW128
        cuuint32_t es[2]      = {1, 1};
        enc(&madj, CU_TENSOR_MAP_DATA_TYPE_FLOAT32, 2, (void*)adj,
            dims, strides, box, es,
            CU_TENSOR_MAP_INTERLEAVE_NONE, CU_TENSOR_MAP_SWIZZLE_128B,
            CU_TENSOR_MAP_L2_PROMOTION_L2_128B, CU_TENSOR_MAP_FLOAT_OOB_FILL_NONE);
    }
    {
        // prefetch-only map: big box (256 cols x 128 rows = 128KB), no swizzle
        cuuint64_t dims[2]    = {(cuuint64_t)K_DIM, (cuuint64_t)N_ROWS};
        cuuint64_t strides[1] = {(cuuint64_t)K_DIM * sizeof(float)};
        cuuint32_t box[2]     = {256, TILE_M};
        cuuint32_t es[2]      = {1, 1};
        enc(&mpref, CU_TENSOR_MAP_DATA_TYPE_FLOAT32, 2, (void*)adj,
            dims, strides, box, es,
            CU_TENSOR_MAP_INTERLEAVE_NONE, CU_TENSOR_MAP_SWIZZLE_NONE,
            CU_TENSOR_MAP_L2_PROMOTION_L2_128B, CU_TENSOR_MAP_FLOAT_OOB_FILL_NONE);
    }
    {
        cuuint64_t dims[2]    = {(cuuint64_t)K_DIM, (cuuint64_t)OUT_F};
        cuuint64_t strides[1] = {(cuuint64_t)K_DIM * sizeof(__half)};
        cuuint32_t box[2]     = {64, OUT_F};        // 64 fp16 = 128B x 64 rows, SW128
        cuuint32_t es[2]      = {1, 1};
        enc(&msup, CU_TENSOR_MAP_DATA_TYPE_FLOAT16, 2, (void*)supT,
            dims, strides, box, es,
            CU_TENSOR_MAP_INTERLEAVE_NONE, CU_TENSOR_MAP_SWIZZLE_128B,
            CU_TENSOR_MAP_L2_PROMOTION_L2_128B, CU_TENSOR_MAP_FLOAT_OOB_FILL_NONE);
    }

    cudaFuncSetAttribute(gcn_gemm_kernel, cudaFuncAttributeMaxDynamicSharedMemorySize,
                         SMEM_BYTES);
    gcn_gemm_kernel<<<N_ROWS / TILE_M, 288, SMEM_BYTES>>>(madj, msup, mpref,
                                                          out, bias, x, w);
}

// round 14
// speedup vs baseline: 1.0916x; 1.0282x over previous
#include <cuda_runtime.h>
#include <cuda.h>
#include <cuda_fp16.h>
#include <cstdint>

// ============================================================================
// GraphConvolution: out = adj[16384,16384] @ (x[16384,64] @ W[64,64]) + bias
//
// Round 14 = Round 13 with a faster supT prologue:
//  (a) packed fma.rn.f32x2 (SASS FFMA2): halves prologue FMA instructions,
//      bit-identical per-lane rn arithmetic
//  (b) per-thread __threadfence removed: stores -> bar.sync (happens-before)
//      -> t0 atom.add.release.gpu is the standard release pattern; the 8
//      warp-wide MEMBAR.GPUs were redundant
// Mainloop / epilogue / prefetch identical to round 13 (gemm at DRAM ceiling).
// ============================================================================

#define N_ROWS 16384
#define K_DIM  16384
#define IN_F   64
#define OUT_F  64

#define TILE_M 128
#define TILE_K 64
#define STAGES 5
#define N_ITERS (K_DIM / TILE_K)        // 256

#define OFF_A0 0                        // 128 rows x 128B (k 0-31)  = 16384
#define OFF_A1 16384                    // 128 rows x 128B (k 32-63) = 16384
#define OFF_B  32768                    // 64 rows x 128B (fp16 k64) = 8192
#define STAGE_BYTES 40960

#define OFF_BARS   0                    // per stage: full @ 16*s, empty @ 16*s+8
#define OFF_TARGET 128                  // u32: epoch target from t0 to producer
#define OFF_TILES  1024
#define OFF_W      (OFF_TILES + STAGES * STAGE_BYTES)        // 205824
#define SMEM_BYTES (OFF_W + IN_F * OUT_F * 4)                // 222208

#define N_CWARPS 8
#define PART_STRIDE 66                  // padded row stride (floats)

#define PREF_BOXES 4                    // 4 x 256 cols x 128 rows fp32 = 512KB/CTA

// ---------------------------------------------------------------- PTX helpers
__device__ __forceinline__ uint32_t smem_to_u32(const void* p) {
    uint32_t a;
    asm("{ .reg .u64 t; cvta.to.shared.u64 t, %1; cvt.u32.u64 %0, t; }" : "=r"(a) : "l"(p));
    return a;
}

#define MBARRIER_INIT(addr, count) \
    asm volatile("mbarrier.init.shared.b64 [%0], %1;" :: "r"((uint32_t)(addr)), "r"((uint32_t)(count)) : "memory")

#define MBARRIER_ARRIVE(addr) \
    asm volatile("mbarrier.arrive.shared.b64 _, [%0];" :: "r"((uint32_t)(addr)) : "memory")

#define MBARRIER_EXPECT_TX(addr, bytes) \
    asm volatile("mbarrier.arrive.expect_tx.shared.b64 _, [%0], %1;" :: "r"((uint32_t)(addr)), "r"((uint32_t)(bytes)) : "memory")

#define MBARRIER_WAIT_PARITY(addr, parity) do {                                      \
    uint32_t _mbar = (uint32_t)(addr);                                               \
    uint32_t _par  = (uint32_t)(parity);                                             \
    uint32_t _done;                                                                  \
    asm volatile(                                                                    \
        "{\n\t.reg .pred p;\n\t"                                                     \
        "mbarrier.try_wait.parity.acquire.cta.shared::cta.b64 p, [%1], %2;\n\t"      \
        "selp.b32 %0, 1, 0, p;\n\t}"                                                 \
        : "=r"(_done) : "r"(_mbar), "r"(_par) : "memory");                           \
    if (!_done) {                                                                    \
        asm volatile(                                                                \
            "{\n\t.reg .pred P1;\n\t"                                                \
            "WAIT_LOOP_%=:\n\t"                                                      \
            "mbarrier.try_wait.parity.acquire.cta.shared::cta.b64 P1, [%0], %1, 0x989680;\n\t" \
            "@P1 bra.uni WAIT_DONE_%=;\n\t"                                          \
            "bra.uni WAIT_LOOP_%=;\n\t"                                              \
            "WAIT_DONE_%=:\n\t}"                                                     \
            :: "r"(_mbar), "r"(_par) : "memory");                                    \
    }                                                                                \
} while (0)

__device__ __forceinline__ void tma_load_2d_g(uint32_t smem_addr, const CUtensorMap* map,
                                              int cx, int cy, uint32_t mbar) {
    asm volatile(
        "cp.async.bulk.tensor.2d.shared::cta.global.tile.mbarrier::complete_tx::bytes "
        "[%0], [%1, {%2, %3}], [%4];"
        :: "r"(smem_addr), "l"(map), "r"(cx), "r"(cy), "r"(mbar) : "memory");
}

__device__ __forceinline__ void tma_prefetch_l2(const CUtensorMap* map, int cx, int cy) {
    asm volatile(
        "cp.async.bulk.prefetch.tensor.2d.L2.global.tile [%0, {%1, %2}];"
        :: "l"(map), "r"(cx), "r"(cy) : "memory");
}

__device__ __forceinline__ uint32_t lds32(uint32_t a) {
    uint32_t v;
    asm volatile("ld.shared.b32 %0, [%1];" : "=r"(v) : "r"(a));
    return v;
}

__device__ __forceinline__ float2 lds64(uint32_t a) {
    float2 v;
    asm volatile("ld.shared.v2.f32 {%0, %1}, [%2];" : "=f"(v.x), "=f"(v.y) : "r"(a));
    return v;
}

// pack two fp32 -> fp16x2: result.lo = lo, result.hi = hi
__device__ __forceinline__ uint32_t packh2(float hi, float lo) {
    uint32_t d;
    asm("cvt.rn.f16x2.f32 %0, %1, %2;" : "=r"(d) : "f"(hi), "f"(lo));
    return d;
}

// ---- packed f32x2 helpers (SASS FFMA2; PTX-only pattern) ----
__device__ __forceinline__ uint64_t pack2f(float lo, float hi) {
    uint64_t d;
    asm("mov.b64 %0, {%1, %2};" : "=l"(d) : "f"(lo), "f"(hi));
    return d;
}
__device__ __forceinline__ uint64_t bcast2f(float v) {
    uint64_t d;
    asm("mov.b64 %0, {%1, %1};" : "=l"(d) : "f"(v));
    return d;
}
#define FMA2(acc, a, b) \
    asm("fma.rn.f32x2 %0, %1, %2, %0;" : "+l"(acc) : "l"(a), "l"(b))
__device__ __forceinline__ void unpack2f(uint64_t v, float& lo, float& hi) {
    asm("mov.b64 {%0, %1}, %2;" : "=f"(lo), "=f"(hi) : "l"(v));
}

__device__ __forceinline__ void mma_f16(float* c,
                                        uint32_t a0, uint32_t a1, uint32_t a2, uint32_t a3,
                                        uint32_t b0, uint32_t b1) {
    asm volatile(
        "mma.sync.aligned.m16n8k16.row.col.f32.f16.f16.f32 "
        "{%0,%1,%2,%3}, {%4,%5,%6,%7}, {%8,%9}, {%0,%1,%2,%3};"
        : "+f"(c[0]), "+f"(c[1]), "+f"(c[2]), "+f"(c[3])
        : "r"(a0), "r"(a1), "r"(a2), "r"(a3), "r"(b0), "r"(b1));
}

// ---------------------------------------------------------------- scratch
__device__ __align__(1024) __half g_supT[(size_t)OUT_F * K_DIM];  // 2 MiB
__device__ unsigned int g_ready;   // monotonic; target via epoch math

// ---------------------------------------------------------------- kernel
// 9 warps: wid 0..7 compute (4 row groups x 2 kgroups) + supT prologue,
// wid 8 = TMA producer (pre-issues A + L2 prefetch, defers B until ready).
__global__ void __launch_bounds__(288, 1) gcn_gemm_kernel(
    const __grid_constant__ CUtensorMap madj,
    const __grid_constant__ CUtensorMap msup,
    const __grid_constant__ CUtensorMap mpref,
    float* __restrict__ out,
    const float* __restrict__ bias,
    const float* __restrict__ x,
    const float* __restrict__ w)
{
    extern __shared__ char smem[];
    uint32_t sb = smem_to_u32(smem);
    int tid = threadIdx.x;
    int wid = tid >> 5;
    int lid = tid & 31;
    int m0 = blockIdx.x * TILE_M;

    if (tid == 0) {
        asm volatile("st.shared.u32 [%0], 0;" :: "r"(sb + OFF_TARGET));
        for (int s = 0; s < STAGES; s++) {
            MBARRIER_INIT(sb + OFF_BARS + s * 16, 1);            // full: 1 expect_tx
            MBARRIER_INIT(sb + OFF_BARS + s * 16 + 8, N_CWARPS); // empty: 8 arrives
        }
    }
    __syncthreads();

    if (wid == 8) {
        if (lid == 0) {
            // ---- pre-issue: expect_tx + A loads for ALL stages (B deferred)
            for (int s = 0; s < STAGES; s++) {
                uint32_t fb = sb + OFF_BARS + s * 16;
                MBARRIER_EXPECT_TX(fb, STAGE_BYTES);
                uint32_t st = sb + OFF_TILES + s * STAGE_BYTES;
                tma_load_2d_g(st + OFF_A0, &madj, s * TILE_K,      m0, fb);
                tma_load_2d_g(st + OFF_A1, &madj, s * TILE_K + 32, m0, fb);
            }
            // ---- L2 prefetch of A for iters 5..20 (fills prologue DRAM idle)
            for (int pb = 0; pb < PREF_BOXES; pb++)
                tma_prefetch_l2(&mpref, STAGES * TILE_K + pb * 256, m0);
            // ---- wait for this CTA's epoch target (from t0)
            unsigned target;
            do {
                asm volatile("ld.acquire.cta.shared.u32 %0, [%1];"
                             : "=r"(target) : "r"(sb + OFF_TARGET));
            } while (target == 0);
            // ---- wait for all 128 CTAs to publish their supT slabs
            unsigned v;
            do {
                asm volatile("ld.acquire.gpu.global.u32 %0, [%1];"
                             : "=r"(v) : "l"(&g_ready));
            } while (v < target);
            asm volatile("fence.proxy.async;" ::: "memory");
            // ---- deferred B loads for the pre-issued stages
            for (int s = 0; s < STAGES; s++) {
                uint32_t fb = sb + OFF_BARS + s * 16;
                uint32_t st = sb + OFF_TILES + s * STAGE_BYTES;
                tma_load_2d_g(st + OFF_B, &msup, s * TILE_K, 0, fb);
            }
            // ---- steady-state pipeline
            int s = 0; uint32_t ph = 0;
            for (int it = STAGES; it < N_ITERS; it++) {
                uint32_t fb = sb + OFF_BARS + s * 16;
                MBARRIER_WAIT_PARITY(fb + 8, ph);
                MBARRIER_EXPECT_TX(fb, STAGE_BYTES);
                uint32_t st = sb + OFF_TILES + s * STAGE_BYTES;
                int k0 = it * TILE_K;
                tma_load_2d_g(st + OFF_B,  &msup, k0,      0,  fb);
                tma_load_2d_g(st + OFF_A0, &madj, k0,      m0, fb);
                tma_load_2d_g(st + OFF_A1, &madj, k0 + 32, m0, fb);
                if (++s == STAGES) { s = 0; ph ^= 1; }
            }
        }
        return;
    }

    // ======== supT prologue (256 compute threads, packed f32x2 FMA) ========
    {
        // stage W into smem, coalesced
        for (int i = tid; i < IN_F * OUT_F / 4; i += 256)
            reinterpret_cast<float4*>(smem + OFF_W)[i] =
                reinterpret_cast<const float4*>(w)[i];
        asm volatile("bar.sync 2, 256;" ::: "memory");

        int p  = tid & 63;            // k-pair index
        int ng = tid >> 6;            // 0..3 -> 16-wide n group
        int n0 = ng * 16;
        size_t k0 = (size_t)blockIdx.x * 128 + 2u * (unsigned)p;
        const float4* xa4 = reinterpret_cast<const float4*>(x + k0 * IN_F);
        const float4* xb4 = reinterpret_cast<const float4*>(x + (k0 + 1) * IN_F);
        const float4* wv  = reinterpret_cast<const float4*>(smem + OFF_W) + (n0 >> 2);

        // 8 packed accumulators per row: accA[jj] = cols (n0+2jj, n0+2jj+1)
        uint64_t accA[8], accB[8];
#pragma unroll
        for (int j = 0; j < 8; j++) { accA[j] = 0ull; accB[j] = 0ull; }

#pragma unroll
        for (int ii = 0; ii < IN_F / 4; ii++) {
            float4 xa = xa4[ii], xb = xb4[ii];
#pragma unroll
            for (int u = 0; u < 4; u++) {
                int i = ii * 4 + u;
                float va = (u == 0) ? xa.x : (u == 1) ? xa.y : (u == 2) ? xa.z : xa.w;
                float vb = (u == 0) ? xb.x : (u == 1) ? xb.y : (u == 2) ? xb.z : xb.w;
                uint64_t vaP = bcast2f(va);
                uint64_t vbP = bcast2f(vb);
                const float4* wr = wv + i * (OUT_F / 4);
#pragma unroll
                for (int j = 0; j < 4; j++) {
                    float4 q = wr[j];
                    uint64_t w0 = pack2f(q.x, q.y);
                    uint64_t w1 = pack2f(q.z, q.w);
                    FMA2(accA[2 * j],     vaP, w0);
                    FMA2(accA[2 * j + 1], vaP, w1);
                    FMA2(accB[2 * j],     vbP, w0);
                    FMA2(accB[2 * j + 1], vbP, w1);
                }
            }
        }
        // write 16 fp16x2 (k0 even -> .lo = k0 row, .hi = k0+1 row)
        uint32_t* dst = reinterpret_cast<uint32_t*>(g_supT);
        size_t kh = k0 >> 1;
#pragma unroll
        for (int jj = 0; jj < 8; jj++) {
            float aLo, aHi, bLo, bHi;
            unpack2f(accA[jj], aLo, aHi);   // row k0:   cols 2jj, 2jj+1
            unpack2f(accB[jj], bLo, bHi);   // row k0+1: cols 2jj, 2jj+1
            dst[(size_t)(n0 + 2 * jj)     * (K_DIM / 2) + kh] = packh2(bLo, aLo);
            dst[(size_t)(n0 + 2 * jj + 1) * (K_DIM / 2) + kh] = packh2(bHi, aHi);
        }

        // release pattern: stores -> bar (happens-before) -> t0 release atomic
        asm volatile("bar.sync 2, 256;" ::: "memory");
        if (tid == 0) {
            unsigned my;
            asm volatile("atom.add.release.gpu.global.u32 %0, [%1], 1;"
                         : "=r"(my) : "l"(&g_ready) : "memory");
            unsigned target = ((my >> 7) + 1) << 7;   // 128 * (replay_epoch + 1)
            asm volatile("st.release.cta.shared.u32 [%0], %1;"
                         :: "r"(sb + OFF_TARGET), "r"(target) : "memory");
        }
    }

    // ======== mainloop (round-8 structure, unchanged) ========
    int cwid   = wid & 3;      // row group: rows [32*cwid, 32*cwid+32)
    int kgroup = wid >> 2;     // owns k32 half: 0 -> k0-31, 1 -> k32-63
    int g = lid >> 2;          // 0..7
    int t = lid & 3;           // 0..3
    uint32_t xorv = (uint32_t)g << 4;   // SW128 swizzle term (rows used == g mod 8)

    uint32_t rA0 = (uint32_t)(cwid * 32 + g) * 128;
    uint32_t rB[8];
#pragma unroll
    for (int nt = 0; nt < 8; nt++) rB[nt] = (uint32_t)(nt * 8 + g) * 128;

    uint32_t cA0[2], cA1[2], cB0[2], cB1[2];
#pragma unroll
    for (int ks2 = 0; ks2 < 2; ks2++) {
        cA0[ks2] = ((uint32_t)(ks2 * 64 + 8 * t))      ^ xorv;
        cA1[ks2] = ((uint32_t)(ks2 * 64 + 8 * t + 32)) ^ xorv;
        uint32_t kk = (uint32_t)(kgroup * 2 + ks2);
        cB0[ks2] = (kk * 32 + 4 * t)      ^ xorv;
        cB1[ks2] = (kk * 32 + 4 * t + 16) ^ xorv;
    }

    float acc[2][8][4];
#pragma unroll
    for (int mt = 0; mt < 2; mt++)
#pragma unroll
        for (int nt = 0; nt < 8; nt++)
#pragma unroll
            for (int c = 0; c < 4; c++) acc[mt][nt][c] = 0.f;

    int s = 0; uint32_t ph = 0;
    for (int it = 0; it < N_ITERS; it++) {
        uint32_t fb = sb + OFF_BARS + s * 16;
        MBARRIER_WAIT_PARITY(fb, ph);
        uint32_t st = sb + OFF_TILES + s * STAGE_BYTES;
        uint32_t aB = st + (kgroup ? OFF_A1 : OFF_A0);
        uint32_t bB = st + OFF_B;

#pragma unroll
        for (int ks2 = 0; ks2 < 2; ks2++) {
            uint32_t a0, a1, a2, a3, a4, a5, a6, a7;
            float2 p;
            p = lds64(aB + rA0 +        cA0[ks2]); a0 = packh2(p.y, p.x);
            p = lds64(aB + rA0 + 1024 + cA0[ks2]); a1 = packh2(p.y, p.x);
            p = lds64(aB + rA0 +        cA1[ks2]); a2 = packh2(p.y, p.x);
            p = lds64(aB + rA0 + 1024 + cA1[ks2]); a3 = packh2(p.y, p.x);
            p = lds64(aB + rA0 + 2048 + cA0[ks2]); a4 = packh2(p.y, p.x);
            p = lds64(aB + rA0 + 3072 + cA0[ks2]); a5 = packh2(p.y, p.x);
            p = lds64(aB + rA0 + 2048 + cA1[ks2]); a6 = packh2(p.y, p.x);
            p = lds64(aB + rA0 + 3072 + cA1[ks2]); a7 = packh2(p.y, p.x);

#pragma unroll
            for (int nt = 0; nt < 8; nt++) {
                uint32_t b0 = lds32(bB + rB[nt] + cB0[ks2]);
                uint32_t b1 = lds32(bB + rB[nt] + cB1[ks2]);
                mma_f16(acc[0][nt], a0, a1, a2, a3, b0, b1);
                mma_f16(acc[1][nt], a4, a5, a6, a7, b0, b1);
            }
        }
        if (lid == 0) MBARRIER_ARRIVE(fb + 8);
        if (++s == STAGES) { s = 0; ph ^= 1; }
    }

    // -------- drain barrier: all compute warps done reading tile smem
    asm volatile("bar.sync 1, 256;" ::: "memory");

    // -------- reduction: kgroup 1 writes partials to smem, kgroup 0 adds
    float* part = reinterpret_cast<float*>(smem + OFF_TILES);
    if (kgroup == 1) {
#pragma unroll
        for (int mt = 0; mt < 2; mt++) {
            int r0 = cwid * 32 + mt * 16 + g;
#pragma unroll
            for (int nt = 0; nt < 8; nt++) {
                int col = nt * 8 + 2 * t;
                *reinterpret_cast<float2*>(part + (size_t)r0 * PART_STRIDE + col) =
                    make_float2(acc[mt][nt][0], acc[mt][nt][1]);
                *reinterpret_cast<float2*>(part + (size_t)(r0 + 8) * PART_STRIDE + col) =
                    make_float2(acc[mt][nt][2], acc[mt][nt][3]);
            }
        }
    }
    asm volatile("bar.sync 1, 256;" ::: "memory");

    if (kgroup == 0) {
        const float2* b2 = reinterpret_cast<const float2*>(bias);
        int row0 = m0 + cwid * 32 + g;
#pragma unroll
        for (int mt = 0; mt < 2; mt++) {
            int rloc = cwid * 32 + mt * 16 + g;
            int r = row0 + mt * 16;
#pragma unroll
            for (int nt = 0; nt < 8; nt++) {
                int col = nt * 8 + 2 * t;
                float2 bv = b2[col >> 1];
                float2 p0 = *reinterpret_cast<const float2*>(part + (size_t)rloc * PART_STRIDE + col);
                float2 p1 = *reinterpret_cast<const float2*>(part + (size_t)(rloc + 8) * PART_STRIDE + col);
                *reinterpret_cast<float2*>(out + (size_t)r * OUT_F + col) =
                    make_float2(acc[mt][nt][0] + p0.x + bv.x, acc[mt][nt][1] + p0.y + bv.y);
                *reinterpret_cast<float2*>(out + (size_t)(r + 8) * OUT_F + col) =
                    make_float2(acc[mt][nt][2] + p1.x + bv.x, acc[mt][nt][3] + p1.y + bv.y);
            }
        }
    }
}

// ---------------------------------------------------------------- host
typedef CUresult (*tmap_encode_fn)(
    CUtensorMap*, CUtensorMapDataType, cuuint32_t, void*,
    const cuuint64_t*, const cuuint64_t*, const cuuint32_t*, const cuuint32_t*,
    CUtensorMapInterleave, CUtensorMapSwizzle, CUtensorMapL2promotion,
    CUtensorMapFloatOOBfill);

extern "C" void kernel_launch(void* const* d_in, const int* in_sizes, int n_in,
                              void* d_out, int out_size) {
    const float* x    = (const float*)d_in[0];
    const float* adj  = (const float*)d_in[1];
    const float* w    = (const float*)d_in[2];
    const float* bias = (const float*)d_in[3];
    float* out = (float*)d_out;

    void* supT_ptr = nullptr;
    cudaGetSymbolAddress(&supT_ptr, g_supT);
    __half* supT = (__half*)supT_ptr;

    // Driver entry point via cudart (no -lcuda link dependency)
    tmap_encode_fn enc = nullptr;
    cudaDriverEntryPointQueryResult qr;
    cudaGetDriverEntryPointByVersion("cuTensorMapEncodeTiled", (void**)&enc, 12000,
                                     cudaEnableDefault, &qr);

    CUtensorMap madj{}, msup{}, mpref{};
    {
        cuuint64_t dims[2]    = {(cuuint64_t)K_DIM, (cuuint64_t)N_ROWS};
        cuuint64_t strides[1] = {(cuuint64_t)K_DIM * sizeof(float)};
        cuuint32_t box[2]     = {32, TILE_M};       // 128B x 128 rows, SW128
        cuuint32_t es[2]      = {1, 1};
        enc(&madj, CU_TENSOR_MAP_DATA_TYPE_FLOAT32, 2, (void*)adj,
            dims, strides, box, es,
            CU_TENSOR_MAP_INTERLEAVE_NONE, CU_TENSOR_MAP_SWIZZLE_128B,
            CU_TENSOR_MAP_L2_PROMOTION_L2_128B, CU_TENSOR_MAP_FLOAT_OOB_FILL_NONE);
    }
    {
        // prefetch-only map: big box (256 cols x 128 rows = 128KB), no swizzle
        cuuint64_t dims[2]    = {(cuuint64_t)K_DIM, (cuuint64_t)N_ROWS};
        cuuint64_t strides[1] = {(cuuint64_t)K_DIM * sizeof(float)};
        cuuint32_t box[2]     = {256, TILE_M};
        cuuint32_t es[2]      = {1, 1};
        enc(&mpref, CU_TENSOR_MAP_DATA_TYPE_FLOAT32, 2, (void*)adj,
            dims, strides, box, es,
            CU_TENSOR_MAP_INTERLEAVE_NONE, CU_TENSOR_MAP_SWIZZLE_NONE,
            CU_TENSOR_MAP_L2_PROMOTION_L2_128B, CU_TENSOR_MAP_FLOAT_OOB_FILL_NONE);
    }
    {
        cuuint64_t dims[2]    = {(cuuint64_t)K_DIM, (cuuint64_t)OUT_F};
        cuuint64_t strides[1] = {(cuuint64_t)K_DIM * sizeof(__half)};
        cuuint32_t box[2]     = {64, OUT_F};        // 64 fp16 = 128B x 64 rows, SW128
        cuuint32_t es[2]      = {1, 1};
        enc(&msup, CU_TENSOR_MAP_DATA_TYPE_FLOAT16, 2, (void*)supT,
            dims, strides, box, es,
            CU_TENSOR_MAP_INTERLEAVE_NONE, CU_TENSOR_MAP_SWIZZLE_128B,
            CU_TENSOR_MAP_L2_PROMOTION_L2_128B, CU_TENSOR_MAP_FLOAT_OOB_FILL_NONE);
    }

    cudaFuncSetAttribute(gcn_gemm_kernel, cudaFuncAttributeMaxDynamicSharedMemorySize,
                         SMEM_BYTES);
    gcn_gemm_kernel<<<N_ROWS / TILE_M, 288, SMEM_BYTES>>>(madj, msup, mpref,
                                                          out, bias, x, w);
}